// round 14
// baseline (speedup 1.0000x reference)
#include <cuda_runtime.h>
#include <cuda_bf16.h>
#include <math.h>
#include <stdint.h>

#define NMAX 1000000
#define BMAX 16384

__device__ float g_t[BMAX * 64];        // t = u @ W1b + b1           [B,64]
__device__ float g_e[NMAX];             // exp(score) per node        [N]
__device__ float g_num[BMAX * 128];     // segmented sum e*x          [B,128]
__device__ float g_den[BMAX];           // segmented sum e            [B]
__device__ float g_x2[BMAX * 256];      // concat(u, pooled)          [B,256]
__device__ float g_h2[BMAX * 256];      // relu(x2@Wg1+bg1)           [B,256]

// ================= helpers =================
__device__ __forceinline__ uint32_t smem_u32(const void* p) {
    uint32_t a;
    asm("{ .reg .u64 t; cvta.to.shared.u64 t, %1; cvt.u32.u64 %0, t; }" : "=r"(a) : "l"(p));
    return a;
}

__device__ __forceinline__ void ldmat4(uint32_t* r, uint32_t addr) {
    asm volatile("ldmatrix.sync.aligned.m8n8.x4.shared.b16 {%0,%1,%2,%3}, [%4];"
        : "=r"(r[0]), "=r"(r[1]), "=r"(r[2]), "=r"(r[3]) : "r"(addr));
}

__device__ __forceinline__ void hmma(float* c, const uint32_t* a, uint32_t b0, uint32_t b1) {
    asm volatile(
        "mma.sync.aligned.m16n8k16.row.col.f32.bf16.bf16.f32 "
        "{%0,%1,%2,%3}, {%4,%5,%6,%7}, {%8,%9}, {%0,%1,%2,%3};"
        : "+f"(c[0]), "+f"(c[1]), "+f"(c[2]), "+f"(c[3])
        : "r"(a[0]), "r"(a[1]), "r"(a[2]), "r"(a[3]), "r"(b0), "r"(b1));
}

// split one float4 to bf16 hi/lo packed pairs
__device__ __forceinline__ void split4(float4 v, uint2& hp, uint2& lp) {
    __nv_bfloat162 h01 = __floats2bfloat162_rn(v.x, v.y);
    __nv_bfloat162 h23 = __floats2bfloat162_rn(v.z, v.w);
    __nv_bfloat162 l01 = __floats2bfloat162_rn(v.x - __low2float(h01), v.y - __high2float(h01));
    __nv_bfloat162 l23 = __floats2bfloat162_rn(v.z - __low2float(h23), v.w - __high2float(h23));
    hp = make_uint2(*(uint32_t*)&h01, *(uint32_t*)&h23);
    lp = make_uint2(*(uint32_t*)&l01, *(uint32_t*)&l23);
}

// ================= zero accumulators =================
__global__ void zero_kernel(int B) {
    int i = blockIdx.x * blockDim.x + threadIdx.x;
    int total = B * 128 + B;
    if (i < B * 128) g_num[i] = 0.f;
    else if (i < total) g_den[i - B * 128] = 0.f;
}

// ================= shared tile geometry =================
#define A_STRIDE   272
#define A_TILE_B   (128 * A_STRIDE)           // 34816 (128-row tile)

#define GB_AH 0
#define GB_AL A_TILE_B
#define GB_BH (2 * A_TILE_B)                  // 69632
#define GB_BL (GB_BH + 32768)                 // 102400
#define GB_TOTAL (GB_BL + 32768)              // 135168

// ---- shared pieces for the GEMM family ----
__device__ __forceinline__ void gemm_pack_B(
    char* smem, const float* __restrict__ Bw, int Nn, int K, int nBase, int tid)
{
    int nEnt = (K >> 4) * 256;
    for (int i = tid; i < nEnt; i += 256) {
        int li = i & 31, nt = (i >> 5) & 7, kcc = i >> 8;
        int n = nBase + nt * 8 + (li >> 2);
        int k0 = kcc * 16 + 2 * (li & 3);
        float w00 = Bw[(size_t)k0 * Nn + n],       w01 = Bw[(size_t)(k0 + 1) * Nn + n];
        float w10 = Bw[(size_t)(k0 + 8) * Nn + n], w11 = Bw[(size_t)(k0 + 9) * Nn + n];
        __nv_bfloat162 h0 = __floats2bfloat162_rn(w00, w01);
        __nv_bfloat162 h1 = __floats2bfloat162_rn(w10, w11);
        __nv_bfloat162 l0 = __floats2bfloat162_rn(w00 - __low2float(h0), w01 - __high2float(h0));
        __nv_bfloat162 l1 = __floats2bfloat162_rn(w10 - __low2float(h1), w11 - __high2float(h1));
        ((uint2*)(smem + GB_BH))[i] = make_uint2(*(uint32_t*)&h0, *(uint32_t*)&h1);
        ((uint2*)(smem + GB_BL))[i] = make_uint2(*(uint32_t*)&l0, *(uint32_t*)&l1);
    }
}

__device__ __forceinline__ void gemm_mma_chunk(
    char* smem, uint32_t sbase, float acc[8][4], int wid, int lane,
    int lrow, int lk, int kcBase)
{
    uint32_t aH = sbase + GB_AH + (wid * 16 + lrow) * A_STRIDE + lk;
    uint32_t aL = aH + A_TILE_B;
#pragma unroll
    for (int kcc = 0; kcc < 8; kcc++) {
        uint32_t ah[4], al[4];
        ldmat4(ah, aH + kcc * 32);
        ldmat4(al, aL + kcc * 32);
        const uint2* bh = (const uint2*)(smem + GB_BH) + (kcBase + kcc) * 256 + lane;
        const uint2* bl = (const uint2*)(smem + GB_BL) + (kcBase + kcc) * 256 + lane;
#pragma unroll
        for (int nt = 0; nt < 8; nt++) {
            uint2 bhv = bh[nt * 32];
            uint2 blv = bl[nt * 32];
            hmma(acc[nt], ah, bhv.x, bhv.y);
            hmma(acc[nt], ah, blv.x, blv.y);
            hmma(acc[nt], al, bhv.x, bhv.y);
        }
    }
}

__device__ __forceinline__ void gemm_epilogue(
    float acc[8][4], const float* __restrict__ bias, float* __restrict__ C,
    int Nn, int relu, int mBase, int nBase, int wid, int g, int t)
{
    int row0 = mBase + wid * 16 + g;
    int row1 = row0 + 8;
#pragma unroll
    for (int nt = 0; nt < 8; nt++) {
        int col = nBase + nt * 8 + 2 * t;
        float2 bv = *(const float2*)(bias + col);
        float v00 = acc[nt][0] + bv.x, v01 = acc[nt][1] + bv.y;
        float v10 = acc[nt][2] + bv.x, v11 = acc[nt][3] + bv.y;
        if (relu) {
            v00 = fmaxf(v00, 0.f); v01 = fmaxf(v01, 0.f);
            v10 = fmaxf(v10, 0.f); v11 = fmaxf(v11, 0.f);
        }
        *(float2*)(C + (size_t)row0 * Nn + col) = make_float2(v00, v01);
        *(float2*)(C + (size_t)row1 * Nn + col) = make_float2(v10, v11);
    }
}

// ================= generic HMMA split GEMM =================
__global__ void __launch_bounds__(256) hmma_gemm(
    const float* __restrict__ A, const float* __restrict__ Bw,
    const float* __restrict__ bias, float* __restrict__ C,
    int M, int Nn, int K, int relu)
{
    extern __shared__ __align__(1024) char smem[];
    uint32_t sbase = smem_u32(smem);
    int tid = threadIdx.x, wid = tid >> 5, lane = tid & 31;
    int g = lane >> 2, t = lane & 3;
    int mBase = blockIdx.y * 128, nBase = blockIdx.x * 64;
    int lrow = lane & 15, lk = (lane >> 4) * 16;

    gemm_pack_B(smem, Bw, Nn, K, nBase, tid);

    float acc[8][4];
#pragma unroll
    for (int nt = 0; nt < 8; nt++)
#pragma unroll
        for (int c = 0; c < 4; c++) acc[nt][c] = 0.f;

    for (int kb = 0; kb < K; kb += 128) {
        for (int i = tid; i < 128 * 32; i += 256) {
            int m = i >> 5, c4 = i & 31;
            float4 v = *(const float4*)(A + (size_t)(mBase + m) * K + kb + c4 * 4);
            uint2 hp, lp; split4(v, hp, lp);
            uint32_t off = m * A_STRIDE + c4 * 8;
            *(uint2*)(smem + GB_AH + off) = hp;
            *(uint2*)(smem + GB_AL + off) = lp;
        }
        __syncthreads();
        gemm_mma_chunk(smem, sbase, acc, wid, lane, lrow, lk, kb >> 4);
        __syncthreads();
    }
    gemm_epilogue(acc, bias, C, Nn, relu, mBase, nBase, wid, g, t);
}

// ================= fused scores + softmax-pool kernel v5 ====================
// 128-row tiles, 128 threads (4 warps), each warp owns 32 rows.
// One B-fragment read feeds 6 HMMAs -> B smem traffic halved.
#define SC_AH 0
#define SC_AL A_TILE_B                        // 34816
#define SC_BH (2 * A_TILE_B)                  // 69632
#define SC_BL (SC_BH + 16384)                 // 86016
#define SC_GB (SC_BL + 16384)                 // 102400 (128 ints)
#define SC_TOTAL (SC_GB + 512)                // 102912

__global__ void __launch_bounds__(128, 2) scores_pool_kernel(
    const float* __restrict__ x, const int* __restrict__ batch,
    const float* __restrict__ W1, const float* __restrict__ W2,
    const float* __restrict__ b2, int N)
{
    extern __shared__ __align__(1024) char smem[];
    uint32_t sbase = smem_u32(smem);
    int*   gb = (int*)(smem + SC_GB);
    int tid = threadIdx.x, wid = tid >> 5, lane = tid & 31;
    int g = lane >> 2, t = lane & 3;
    int lrow = lane & 15, lk = (lane >> 4) * 16;

    // pre-pack B = W1a^T fragments (2048 entries)
    for (int i = tid; i < 2048; i += 128) {
        int li = i & 31, nt = (i >> 5) & 7, kc = i >> 8;
        int n = nt * 8 + (li >> 2);
        int k0 = kc * 16 + 2 * (li & 3);
        float w00 = W1[k0 * 64 + n],       w01 = W1[(k0 + 1) * 64 + n];
        float w10 = W1[(k0 + 8) * 64 + n], w11 = W1[(k0 + 9) * 64 + n];
        __nv_bfloat162 h0 = __floats2bfloat162_rn(w00, w01);
        __nv_bfloat162 h1 = __floats2bfloat162_rn(w10, w11);
        __nv_bfloat162 l0 = __floats2bfloat162_rn(w00 - __low2float(h0), w01 - __high2float(h0));
        __nv_bfloat162 l1 = __floats2bfloat162_rn(w10 - __low2float(h1), w11 - __high2float(h1));
        ((uint2*)(smem + SC_BH))[i] = make_uint2(*(uint32_t*)&h0, *(uint32_t*)&h1);
        ((uint2*)(smem + SC_BL))[i] = make_uint2(*(uint32_t*)&l0, *(uint32_t*)&l1);
    }

    float2 w2r[8];
#pragma unroll
    for (int nt = 0; nt < 8; nt++)
        w2r[nt] = *(const float2*)(W2 + nt * 8 + 2 * t);
    float b2v = b2[0];

    int T = (N + 127) >> 7;
    int G = gridDim.x;
    int L = ((int)blockIdx.x < T) ? (T - (int)blockIdx.x + G - 1) / G : 0;

    __syncthreads();

    int mRow = tid >> 5;           // 0..3; rows stride 4
    int c4   = tid & 31;

    for (int j = 0; j < L; j++) {
        long base = ((long)blockIdx.x + (long)j * G) * 128;

        // ---- stage 128-row tile: LDG -> hi/lo cvt -> STS; batch ids ----
#pragma unroll 8
        for (int r = 0; r < 32; r++) {
            int m = mRow + r * 4;
            long gi = base + m;
            float4 v = make_float4(0.f, 0.f, 0.f, 0.f);
            if (gi < N) v = __ldg((const float4*)(x + gi * 128 + c4 * 4));
            uint2 hp, lp; split4(v, hp, lp);
            uint32_t off = m * A_STRIDE + c4 * 8;
            *(uint2*)(smem + SC_AH + off) = hp;
            *(uint2*)(smem + SC_AL + off) = lp;
        }
        {
            long gi = base + tid;
            gb[tid] = (gi < N) ? batch[gi] : 0;
        }
        __syncthreads();

        // ---- HMMA: each warp 32 rows (2 x 16-row groups) ----
        uint32_t aH0 = sbase + SC_AH + (wid * 32 + lrow) * A_STRIDE + lk;
        uint32_t aH1 = aH0 + 16 * A_STRIDE;
        uint32_t aL0 = aH0 + A_TILE_B;
        uint32_t aL1 = aH1 + A_TILE_B;

        float acc[2][8][4];
#pragma unroll
        for (int b = 0; b < 2; b++)
#pragma unroll
            for (int nt = 0; nt < 8; nt++)
#pragma unroll
                for (int c = 0; c < 4; c++) acc[b][nt][c] = 0.f;

#pragma unroll
        for (int kc = 0; kc < 8; kc++) {
            uint32_t ah0[4], ah1[4], al0[4], al1[4];
            ldmat4(ah0, aH0 + kc * 32);
            ldmat4(ah1, aH1 + kc * 32);
            ldmat4(al0, aL0 + kc * 32);
            ldmat4(al1, aL1 + kc * 32);
            const uint2* bh = (const uint2*)(smem + SC_BH) + kc * 256 + lane;
            const uint2* bl = (const uint2*)(smem + SC_BL) + kc * 256 + lane;
#pragma unroll
            for (int nt = 0; nt < 8; nt++) {
                uint2 bhv = bh[nt * 32];
                uint2 blv = bl[nt * 32];
                hmma(acc[0][nt], ah0, bhv.x, bhv.y);
                hmma(acc[0][nt], ah0, blv.x, blv.y);
                hmma(acc[0][nt], al0, bhv.x, bhv.y);
                hmma(acc[1][nt], ah1, bhv.x, bhv.y);
                hmma(acc[1][nt], ah1, blv.x, blv.y);
                hmma(acc[1][nt], al1, bhv.x, bhv.y);
            }
        }

        // ---- epilogue: 4 scores/lane-group -> e; g_e, RED den ----
        int rowBase = wid * 32;
        float e_arr[4];
        {
            int m00 = rowBase + g;            // acc[0][..][0,1]
            int m01 = m00 + 8;                // acc[0][..][2,3]
            int m10 = m00 + 16;               // acc[1][..][0,1]
            int m11 = m00 + 24;               // acc[1][..][2,3]
            const float* t00 = g_t + (size_t)gb[m00] * 64;
            const float* t01 = g_t + (size_t)gb[m01] * 64;
            const float* t10 = g_t + (size_t)gb[m10] * 64;
            const float* t11 = g_t + (size_t)gb[m11] * 64;
            float s00 = 0.f, s01 = 0.f, s10 = 0.f, s11 = 0.f;
#pragma unroll
            for (int nt = 0; nt < 8; nt++) {
                int col = nt * 8 + 2 * t;
                float2 w = w2r[nt];
                float2 v00 = *(const float2*)(t00 + col);
                float2 v01 = *(const float2*)(t01 + col);
                float2 v10 = *(const float2*)(t10 + col);
                float2 v11 = *(const float2*)(t11 + col);
                s00 += fmaxf(acc[0][nt][0] + v00.x, 0.f) * w.x
                     + fmaxf(acc[0][nt][1] + v00.y, 0.f) * w.y;
                s01 += fmaxf(acc[0][nt][2] + v01.x, 0.f) * w.x
                     + fmaxf(acc[0][nt][3] + v01.y, 0.f) * w.y;
                s10 += fmaxf(acc[1][nt][0] + v10.x, 0.f) * w.x
                     + fmaxf(acc[1][nt][1] + v10.y, 0.f) * w.y;
                s11 += fmaxf(acc[1][nt][2] + v11.x, 0.f) * w.x
                     + fmaxf(acc[1][nt][3] + v11.y, 0.f) * w.y;
            }
            s00 += __shfl_xor_sync(0xffffffffu, s00, 1);
            s00 += __shfl_xor_sync(0xffffffffu, s00, 2);
            s01 += __shfl_xor_sync(0xffffffffu, s01, 1);
            s01 += __shfl_xor_sync(0xffffffffu, s01, 2);
            s10 += __shfl_xor_sync(0xffffffffu, s10, 1);
            s10 += __shfl_xor_sync(0xffffffffu, s10, 2);
            s11 += __shfl_xor_sync(0xffffffffu, s11, 1);
            s11 += __shfl_xor_sync(0xffffffffu, s11, 2);
            long r00 = base + m00, r01 = base + m01;
            long r10 = base + m10, r11 = base + m11;
            e_arr[0] = (r00 < N) ? __expf(s00 + b2v) : 0.f;
            e_arr[1] = (r01 < N) ? __expf(s01 + b2v) : 0.f;
            e_arr[2] = (r10 < N) ? __expf(s10 + b2v) : 0.f;
            e_arr[3] = (r11 < N) ? __expf(s11 + b2v) : 0.f;
            if (t == 0) {
                if (r00 < N) { g_e[r00] = e_arr[0]; atomicAdd(g_den + gb[m00], e_arr[0]); }
                if (r01 < N) { g_e[r01] = e_arr[1]; atomicAdd(g_den + gb[m01], e_arr[1]); }
                if (r10 < N) { g_e[r10] = e_arr[2]; atomicAdd(g_den + gb[m10], e_arr[2]); }
                if (r11 < N) { g_e[r11] = e_arr[3]; atomicAdd(g_den + gb[m11], e_arr[3]); }
            }
        }

        // ---- per-warp pooling: 32 rows x 4 feats/lane from smem ----
        {
            float a0 = 0.f, a1 = 0.f, a2 = 0.f, a3 = 0.f;
#pragma unroll
            for (int r = 0; r < 32; r++) {
                int row = rowBase + r;
                float er = __shfl_sync(0xffffffffu, e_arr[r >> 3], (r & 7) * 4);
                uint2 h = *(uint2*)(smem + SC_AH + row * A_STRIDE + lane * 8);
                uint2 l = *(uint2*)(smem + SC_AL + row * A_STRIDE + lane * 8);
                __nv_bfloat162 h0 = *(__nv_bfloat162*)&h.x, h1 = *(__nv_bfloat162*)&h.y;
                __nv_bfloat162 l0 = *(__nv_bfloat162*)&l.x, l1 = *(__nv_bfloat162*)&l.y;
                a0 += er * (__low2float(h0)  + __low2float(l0));
                a1 += er * (__high2float(h0) + __high2float(l0));
                a2 += er * (__low2float(h1)  + __low2float(l1));
                a3 += er * (__high2float(h1) + __high2float(l1));
                int gcur = gb[row];
                if (r == 31 || gb[row + 1] != gcur) {
                    float* dst = g_num + (size_t)gcur * 128 + lane * 4;
                    atomicAdd(dst,     a0);
                    atomicAdd(dst + 1, a1);
                    atomicAdd(dst + 2, a2);
                    atomicAdd(dst + 3, a3);
                    a0 = a1 = a2 = a3 = 0.f;
                }
            }
        }
        __syncthreads();
    }
}

// ================= merged post-processing =================
__global__ void __launch_bounds__(256) post_kernel(
    const float* __restrict__ u, const int* __restrict__ batch,
    float* __restrict__ attn, int N, int B)
{
    int nX2 = B * 32;
    int stride = gridDim.x * blockDim.x;
    for (int i = blockIdx.x * blockDim.x + threadIdx.x; i < nX2; i += stride) {
        int g = i >> 5, q = i & 31;
        float den = g_den[g];
        float inv = (den > 0.f) ? 1.f / den : 0.f;
        float4 uv = *(const float4*)(u + (size_t)g * 128 + q * 4);
        float4 nv = *(const float4*)(g_num + (size_t)g * 128 + q * 4);
        nv.x *= inv; nv.y *= inv; nv.z *= inv; nv.w *= inv;
        *(float4*)(g_x2 + (size_t)g * 256 + q * 4)       = uv;
        *(float4*)(g_x2 + (size_t)g * 256 + 128 + q * 4) = nv;
    }
    for (int i = blockIdx.x * blockDim.x + threadIdx.x; i < N; i += stride) {
        attn[i] = g_e[i] / g_den[batch[i]];
    }
}

// ================= launch =================
extern "C" void kernel_launch(void* const* d_in, const int* in_sizes, int n_in,
                              void* d_out, int out_size)
{
    const float* x     = (const float*)d_in[0];
    const float* u     = (const float*)d_in[3];
    const int*   batch = (const int*)d_in[4];
    const float* W1    = (const float*)d_in[5];
    const float* b1    = (const float*)d_in[6];
    const float* W2    = (const float*)d_in[7];
    const float* b2    = (const float*)d_in[8];
    const float* Wg1   = (const float*)d_in[9];
    const float* bg1   = (const float*)d_in[10];
    const float* Wg2   = (const float*)d_in[11];
    const float* bg2   = (const float*)d_in[12];

    int N = in_sizes[0] / 128;
    int B = in_sizes[3] / 128;

    float* out  = (float*)d_out;
    float* attn = (float*)d_out + (size_t)B * 128;

    float *t_ptr, *x2_ptr, *h2_ptr;
    cudaGetSymbolAddress((void**)&t_ptr,  g_t);
    cudaGetSymbolAddress((void**)&x2_ptr, g_x2);
    cudaGetSymbolAddress((void**)&h2_ptr, g_h2);

    cudaFuncSetAttribute(hmma_gemm,
                         cudaFuncAttributeMaxDynamicSharedMemorySize, GB_TOTAL);
    cudaFuncSetAttribute(scores_pool_kernel,
                         cudaFuncAttributeMaxDynamicSharedMemorySize, SC_TOTAL);

    // 0) zero accumulators
    zero_kernel<<<(B * 129 + 255) / 256, 256>>>(B);

    // 1) t[B,64] = u @ W1b + b1
    {
        dim3 grid(1, B / 128);
        hmma_gemm<<<grid, 256, GB_TOTAL>>>(u, W1 + 128 * 64, b1, t_ptr, B, 64, 128, 0);
    }

    // 2) fused scores + softmax-pool (128-row tiles, 32 rows/warp, 2 CTAs/SM)
    {
        int T = (N + 127) / 128;
        int grid = T < 296 ? T : 296;
        scores_pool_kernel<<<grid, 128, SC_TOTAL>>>(x, batch, W1, W2, b2, N);
    }

    // 3) merged post-processing (x2 build + attn)
    post_kernel<<<1184, 256>>>(u, batch, attn, N, B);

    // 4) global MLP via generic HMMA split
    {
        dim3 g3a(256 / 64, B / 128);
        hmma_gemm<<<g3a, 256, GB_TOTAL>>>(x2_ptr, Wg1, bg1, h2_ptr, B, 256, 256, 1);
        dim3 g3b(128 / 64, B / 128);
        hmma_gemm<<<g3b, 256, GB_TOTAL>>>(h2_ptr, Wg2, bg2, out, B, 128, 256, 0);
    }
}

// round 15
// speedup vs baseline: 1.4313x; 1.4313x over previous
#include <cuda_runtime.h>
#include <cuda_fp16.h>
#include <math.h>
#include <stdint.h>

#define NMAX 1000000
#define BMAX 16384

__device__ float g_t[BMAX * 64];        // t = u @ W1b + b1           [B,64]
__device__ float g_e[NMAX];             // exp(score) per node        [N]
__device__ float g_num[BMAX * 128];     // segmented sum e*x          [B,128]
__device__ float g_den[BMAX];           // segmented sum e            [B]
__device__ float g_x2[BMAX * 256];      // concat(u, pooled)          [B,256]
__device__ float g_h2[BMAX * 256];      // relu(x2@Wg1+bg1)           [B,256]

// ================= helpers =================
__device__ __forceinline__ uint32_t smem_u32(const void* p) {
    uint32_t a;
    asm("{ .reg .u64 t; cvta.to.shared.u64 t, %1; cvt.u32.u64 %0, t; }" : "=r"(a) : "l"(p));
    return a;
}

__device__ __forceinline__ void ldmat4(uint32_t* r, uint32_t addr) {
    asm volatile("ldmatrix.sync.aligned.m8n8.x4.shared.b16 {%0,%1,%2,%3}, [%4];"
        : "=r"(r[0]), "=r"(r[1]), "=r"(r[2]), "=r"(r[3]) : "r"(addr));
}

// fp16 HMMA, fp32 accumulate
__device__ __forceinline__ void hmma(float* c, const uint32_t* a, uint32_t b0, uint32_t b1) {
    asm volatile(
        "mma.sync.aligned.m16n8k16.row.col.f32.f16.f16.f32 "
        "{%0,%1,%2,%3}, {%4,%5,%6,%7}, {%8,%9}, {%0,%1,%2,%3};"
        : "+f"(c[0]), "+f"(c[1]), "+f"(c[2]), "+f"(c[3])
        : "r"(a[0]), "r"(a[1]), "r"(a[2]), "r"(a[3]), "r"(b0), "r"(b1));
}

// split one float4 to fp16 hi/lo packed pairs (x = hi + lo, |lo| ~ 2^-11 |x|)
__device__ __forceinline__ void split4h(float4 v, uint2& hp, uint2& lp) {
    __half2 h01 = __floats2half2_rn(v.x, v.y);
    __half2 h23 = __floats2half2_rn(v.z, v.w);
    float2 f01 = __half22float2(h01);
    float2 f23 = __half22float2(h23);
    __half2 l01 = __floats2half2_rn(v.x - f01.x, v.y - f01.y);
    __half2 l23 = __floats2half2_rn(v.z - f23.x, v.w - f23.y);
    hp = make_uint2(*(uint32_t*)&h01, *(uint32_t*)&h23);
    lp = make_uint2(*(uint32_t*)&l01, *(uint32_t*)&l23);
}

// ================= zero accumulators =================
__global__ void zero_kernel(int B) {
    int i = blockIdx.x * blockDim.x + threadIdx.x;
    int total = B * 128 + B;
    if (i < B * 128) g_num[i] = 0.f;
    else if (i < total) g_den[i - B * 128] = 0.f;
}

// ================= shared tile geometry =================
#define A_STRIDE   272
#define A_TILE_B   (128 * A_STRIDE)           // 34816 (128-row tile, gemms)

#define GB_AH 0
#define GB_AL A_TILE_B
#define GB_B  (2 * A_TILE_B)                  // 69632; single fp16 B, K<=256 -> 32KB
#define GB_TOTAL (GB_B + 32768)               // 102400

// ---- shared pieces for the GEMM family (single fp16 B operand) ----
__device__ __forceinline__ void gemm_pack_B(
    char* smem, const float* __restrict__ Bw, int Nn, int K, int nBase, int tid)
{
    int nEnt = (K >> 4) * 256;
    for (int i = tid; i < nEnt; i += 256) {
        int li = i & 31, nt = (i >> 5) & 7, kcc = i >> 8;
        int n = nBase + nt * 8 + (li >> 2);
        int k0 = kcc * 16 + 2 * (li & 3);
        __half2 b0 = __floats2half2_rn(Bw[(size_t)k0 * Nn + n],       Bw[(size_t)(k0 + 1) * Nn + n]);
        __half2 b1 = __floats2half2_rn(Bw[(size_t)(k0 + 8) * Nn + n], Bw[(size_t)(k0 + 9) * Nn + n]);
        ((uint2*)(smem + GB_B))[i] = make_uint2(*(uint32_t*)&b0, *(uint32_t*)&b1);
    }
}

__device__ __forceinline__ void gemm_mma_chunk(
    char* smem, uint32_t sbase, float acc[8][4], int wid, int lane,
    int lrow, int lk, int kcBase)
{
    uint32_t aH = sbase + GB_AH + (wid * 16 + lrow) * A_STRIDE + lk;
    uint32_t aL = aH + A_TILE_B;
#pragma unroll
    for (int kcc = 0; kcc < 8; kcc++) {
        uint32_t ah[4], al[4];
        ldmat4(ah, aH + kcc * 32);
        ldmat4(al, aL + kcc * 32);
        const uint2* bp = (const uint2*)(smem + GB_B) + (kcBase + kcc) * 256 + lane;
#pragma unroll
        for (int nt = 0; nt < 8; nt++) {
            uint2 bv = bp[nt * 32];
            hmma(acc[nt], ah, bv.x, bv.y);
            hmma(acc[nt], al, bv.x, bv.y);
        }
    }
}

__device__ __forceinline__ void gemm_epilogue(
    float acc[8][4], const float* __restrict__ bias, float* __restrict__ C,
    int Nn, int relu, int mBase, int nBase, int wid, int g, int t)
{
    int row0 = mBase + wid * 16 + g;
    int row1 = row0 + 8;
#pragma unroll
    for (int nt = 0; nt < 8; nt++) {
        int col = nBase + nt * 8 + 2 * t;
        float2 bv = *(const float2*)(bias + col);
        float v00 = acc[nt][0] + bv.x, v01 = acc[nt][1] + bv.y;
        float v10 = acc[nt][2] + bv.x, v11 = acc[nt][3] + bv.y;
        if (relu) {
            v00 = fmaxf(v00, 0.f); v01 = fmaxf(v01, 0.f);
            v10 = fmaxf(v10, 0.f); v11 = fmaxf(v11, 0.f);
        }
        *(float2*)(C + (size_t)row0 * Nn + col) = make_float2(v00, v01);
        *(float2*)(C + (size_t)row1 * Nn + col) = make_float2(v10, v11);
    }
}

// ================= generic fp16-split HMMA GEMM =================
__global__ void __launch_bounds__(256) hmma_gemm(
    const float* __restrict__ A, const float* __restrict__ Bw,
    const float* __restrict__ bias, float* __restrict__ C,
    int M, int Nn, int K, int relu)
{
    extern __shared__ __align__(1024) char smem[];
    uint32_t sbase = smem_u32(smem);
    int tid = threadIdx.x, wid = tid >> 5, lane = tid & 31;
    int g = lane >> 2, t = lane & 3;
    int mBase = blockIdx.y * 128, nBase = blockIdx.x * 64;
    int lrow = lane & 15, lk = (lane >> 4) * 16;

    gemm_pack_B(smem, Bw, Nn, K, nBase, tid);

    float acc[8][4];
#pragma unroll
    for (int nt = 0; nt < 8; nt++)
#pragma unroll
        for (int c = 0; c < 4; c++) acc[nt][c] = 0.f;

    for (int kb = 0; kb < K; kb += 128) {
        for (int i = tid; i < 128 * 32; i += 256) {
            int m = i >> 5, c4 = i & 31;
            float4 v = *(const float4*)(A + (size_t)(mBase + m) * K + kb + c4 * 4);
            uint2 hp, lp; split4h(v, hp, lp);
            uint32_t off = m * A_STRIDE + c4 * 8;
            *(uint2*)(smem + GB_AH + off) = hp;
            *(uint2*)(smem + GB_AL + off) = lp;
        }
        __syncthreads();
        gemm_mma_chunk(smem, sbase, acc, wid, lane, lrow, lk, kb >> 4);
        __syncthreads();
    }
    gemm_epilogue(acc, bias, C, Nn, relu, mBase, nBase, wid, g, t);
}

// ================= fused scores + softmax-pool kernel =================
// 64-row tiles, 128 threads, fp16 2-term split, single B -> 4 CTAs/SM.
#define A64_TILE_B (64 * A_STRIDE)            // 17408
#define SC_AH 0
#define SC_AL A64_TILE_B                      // 17408
#define SC_B  (2 * A64_TILE_B)                // 34816; single fp16 B = 16KB
#define SC_GB (SC_B + 16384)                  // 51200 (64 ints)
#define SC_TOTAL (SC_GB + 256)                // 51456

__global__ void __launch_bounds__(128, 4) scores_pool_kernel(
    const float* __restrict__ x, const int* __restrict__ batch,
    const float* __restrict__ W1, const float* __restrict__ W2,
    const float* __restrict__ b2, int N)
{
    extern __shared__ __align__(1024) char smem[];
    uint32_t sbase = smem_u32(smem);
    int*   gb = (int*)(smem + SC_GB);
    int tid = threadIdx.x, wid = tid >> 5, lane = tid & 31;
    int g = lane >> 2, t = lane & 3;
    int lrow = lane & 15, lk = (lane >> 4) * 16;

    // pre-pack B = W1a^T fragments (single fp16, 2048 entries)
    for (int i = tid; i < 2048; i += 128) {
        int li = i & 31, nt = (i >> 5) & 7, kc = i >> 8;
        int n = nt * 8 + (li >> 2);
        int k0 = kc * 16 + 2 * (li & 3);
        __half2 b0 = __floats2half2_rn(W1[k0 * 64 + n],       W1[(k0 + 1) * 64 + n]);
        __half2 b1 = __floats2half2_rn(W1[(k0 + 8) * 64 + n], W1[(k0 + 9) * 64 + n]);
        ((uint2*)(smem + SC_B))[i] = make_uint2(*(uint32_t*)&b0, *(uint32_t*)&b1);
    }

    float2 w2r[8];
#pragma unroll
    for (int nt = 0; nt < 8; nt++)
        w2r[nt] = *(const float2*)(W2 + nt * 8 + 2 * t);
    float b2v = b2[0];

    int T = (N + 63) >> 6;
    int G = gridDim.x;
    int L = ((int)blockIdx.x < T) ? (T - (int)blockIdx.x + G - 1) / G : 0;

    __syncthreads();

    int mRow = tid >> 5;           // 0..3; rows stride 4
    int c4   = tid & 31;

    for (int j = 0; j < L; j++) {
        long base = ((long)blockIdx.x + (long)j * G) * 64;

        // ---- stage tile (64 rows): LDG -> fp16 hi/lo -> STS; batch ids ----
#pragma unroll
        for (int r = 0; r < 16; r++) {
            int m = mRow + r * 4;
            long gi = base + m;
            float4 v = make_float4(0.f, 0.f, 0.f, 0.f);
            if (gi < N) v = __ldg((const float4*)(x + gi * 128 + c4 * 4));
            uint2 hp, lp; split4h(v, hp, lp);
            uint32_t off = m * A_STRIDE + c4 * 8;
            *(uint2*)(smem + SC_AH + off) = hp;
            *(uint2*)(smem + SC_AL + off) = lp;
        }
        if (tid < 64) {
            long gi = base + tid;
            gb[tid] = (gi < N) ? batch[gi] : 0;
        }
        __syncthreads();

        // ---- HMMA: each warp 16 rows, 2 terms ----
        uint32_t aH = sbase + SC_AH + (wid * 16 + lrow) * A_STRIDE + lk;
        uint32_t aL = aH + A64_TILE_B;
        float acc[8][4];
#pragma unroll
        for (int nt = 0; nt < 8; nt++)
#pragma unroll
            for (int c = 0; c < 4; c++) acc[nt][c] = 0.f;

#pragma unroll
        for (int kc = 0; kc < 8; kc++) {
            uint32_t ah[4], al[4];
            ldmat4(ah, aH + kc * 32);
            ldmat4(al, aL + kc * 32);
            const uint2* bp = (const uint2*)(smem + SC_B) + kc * 256 + lane;
#pragma unroll
            for (int nt = 0; nt < 8; nt++) {
                uint2 bv = bp[nt * 32];
                hmma(acc[nt], ah, bv.x, bv.y);
                hmma(acc[nt], al, bv.x, bv.y);
            }
        }

        // ---- epilogue: e = exp(s); g_e, RED den; per-warp pooling ----
        int m0 = wid * 16 + g;
        int m1 = m0 + 8;
        long r0 = base + m0, r1 = base + m1;
        int bi0 = gb[m0], bi1 = gb[m1];
        {
            const float* t0 = g_t + (size_t)bi0 * 64;
            const float* t1 = g_t + (size_t)bi1 * 64;
            float s0 = 0.f, s1 = 0.f;
#pragma unroll
            for (int nt = 0; nt < 8; nt++) {
                int col = nt * 8 + 2 * t;
                float2 tv0 = *(const float2*)(t0 + col);
                float2 tv1 = *(const float2*)(t1 + col);
                float2 w = w2r[nt];
                s0 += fmaxf(acc[nt][0] + tv0.x, 0.f) * w.x
                    + fmaxf(acc[nt][1] + tv0.y, 0.f) * w.y;
                s1 += fmaxf(acc[nt][2] + tv1.x, 0.f) * w.x
                    + fmaxf(acc[nt][3] + tv1.y, 0.f) * w.y;
            }
            s0 += __shfl_xor_sync(0xffffffffu, s0, 1);
            s0 += __shfl_xor_sync(0xffffffffu, s0, 2);
            s1 += __shfl_xor_sync(0xffffffffu, s1, 1);
            s1 += __shfl_xor_sync(0xffffffffu, s1, 2);
            float e0 = (r0 < N) ? __expf(s0 + b2v) : 0.f;
            float e1 = (r1 < N) ? __expf(s1 + b2v) : 0.f;
            if (t == 0) {
                if (r0 < N) { g_e[r0] = e0; atomicAdd(g_den + bi0, e0); }
                if (r1 < N) { g_e[r1] = e1; atomicAdd(g_den + bi1, e1); }
            }

            // per-warp pooling: 16 rows x 4 feats/lane from smem (x ~ hi+lo)
            float a0 = 0.f, a1 = 0.f, a2 = 0.f, a3 = 0.f;
            int rowBase = wid * 16;
#pragma unroll
            for (int r = 0; r < 16; r++) {
                int row = rowBase + r;
                float er = (r < 8) ? __shfl_sync(0xffffffffu, e0, r * 4)
                                   : __shfl_sync(0xffffffffu, e1, (r - 8) * 4);
                uint2 h = *(uint2*)(smem + SC_AH + row * A_STRIDE + lane * 8);
                uint2 l = *(uint2*)(smem + SC_AL + row * A_STRIDE + lane * 8);
                float2 h0 = __half22float2(*(__half2*)&h.x);
                float2 h1 = __half22float2(*(__half2*)&h.y);
                float2 l0 = __half22float2(*(__half2*)&l.x);
                float2 l1 = __half22float2(*(__half2*)&l.y);
                a0 += er * (h0.x + l0.x);
                a1 += er * (h0.y + l0.y);
                a2 += er * (h1.x + l1.x);
                a3 += er * (h1.y + l1.y);
                int gcur = gb[row];
                if (r == 15 || gb[row + 1] != gcur) {
                    float* dst = g_num + (size_t)gcur * 128 + lane * 4;
                    atomicAdd(dst,     a0);
                    atomicAdd(dst + 1, a1);
                    atomicAdd(dst + 2, a2);
                    atomicAdd(dst + 3, a3);
                    a0 = a1 = a2 = a3 = 0.f;
                }
            }
        }
        __syncthreads();
    }
}

// ================= merged post-processing =================
__global__ void __launch_bounds__(256) post_kernel(
    const float* __restrict__ u, const int* __restrict__ batch,
    float* __restrict__ attn, int N, int B)
{
    int nX2 = B * 32;
    int stride = gridDim.x * blockDim.x;
    for (int i = blockIdx.x * blockDim.x + threadIdx.x; i < nX2; i += stride) {
        int g = i >> 5, q = i & 31;
        float den = g_den[g];
        float inv = (den > 0.f) ? 1.f / den : 0.f;
        float4 uv = *(const float4*)(u + (size_t)g * 128 + q * 4);
        float4 nv = *(const float4*)(g_num + (size_t)g * 128 + q * 4);
        nv.x *= inv; nv.y *= inv; nv.z *= inv; nv.w *= inv;
        *(float4*)(g_x2 + (size_t)g * 256 + q * 4)       = uv;
        *(float4*)(g_x2 + (size_t)g * 256 + 128 + q * 4) = nv;
    }
    for (int i = blockIdx.x * blockDim.x + threadIdx.x; i < N; i += stride) {
        attn[i] = g_e[i] / g_den[batch[i]];
    }
}

// ================= launch =================
extern "C" void kernel_launch(void* const* d_in, const int* in_sizes, int n_in,
                              void* d_out, int out_size)
{
    const float* x     = (const float*)d_in[0];
    const float* u     = (const float*)d_in[3];
    const int*   batch = (const int*)d_in[4];
    const float* W1    = (const float*)d_in[5];
    const float* b1    = (const float*)d_in[6];
    const float* W2    = (const float*)d_in[7];
    const float* b2    = (const float*)d_in[8];
    const float* Wg1   = (const float*)d_in[9];
    const float* bg1   = (const float*)d_in[10];
    const float* Wg2   = (const float*)d_in[11];
    const float* bg2   = (const float*)d_in[12];

    int N = in_sizes[0] / 128;
    int B = in_sizes[3] / 128;

    float* out  = (float*)d_out;
    float* attn = (float*)d_out + (size_t)B * 128;

    float *t_ptr, *x2_ptr, *h2_ptr;
    cudaGetSymbolAddress((void**)&t_ptr,  g_t);
    cudaGetSymbolAddress((void**)&x2_ptr, g_x2);
    cudaGetSymbolAddress((void**)&h2_ptr, g_h2);

    cudaFuncSetAttribute(hmma_gemm,
                         cudaFuncAttributeMaxDynamicSharedMemorySize, GB_TOTAL);
    cudaFuncSetAttribute(scores_pool_kernel,
                         cudaFuncAttributeMaxDynamicSharedMemorySize, SC_TOTAL);

    // 0) zero accumulators
    zero_kernel<<<(B * 129 + 255) / 256, 256>>>(B);

    // 1) t[B,64] = u @ W1b + b1
    {
        dim3 grid(1, B / 128);
        hmma_gemm<<<grid, 256, GB_TOTAL>>>(u, W1 + 128 * 64, b1, t_ptr, B, 64, 128, 0);
    }

    // 2) fused scores + softmax-pool (64-row tiles, fp16 2-term, 4 CTAs/SM)
    {
        int T = (N + 63) / 64;
        int grid = T < 592 ? T : 592;
        scores_pool_kernel<<<grid, 128, SC_TOTAL>>>(x, batch, W1, W2, b2, N);
    }

    // 3) merged post-processing (x2 build + attn)
    post_kernel<<<1184, 256>>>(u, batch, attn, N, B);

    // 4) global MLP via fp16-split HMMA
    {
        dim3 g3a(256 / 64, B / 128);
        hmma_gemm<<<g3a, 256, GB_TOTAL>>>(x2_ptr, Wg1, bg1, h2_ptr, B, 256, 256, 1);
        dim3 g3b(128 / 64, B / 128);
        hmma_gemm<<<g3b, 256, GB_TOTAL>>>(h2_ptr, Wg2, bg2, out, B, 128, 256, 0);
    }
}